// round 17
// baseline (speedup 1.0000x reference)
#include <cuda_runtime.h>
#include <stdint.h>

// Seq2seq LSTM, persistent kernel, FMA-bound register-tile GEMM. v2:
// - hv hoisted 4 at a time (2 halves) and Wih/bias in smem -> no spills (was regs=255)
// - decoder y-feedback reduction parallelized across all 256 threads
// 128 blocks x 256 threads. Block owns 16 units (64 gate rows) x 32 batches.
// k split across 8 warps; thread = 8 rows x 8 batches packed-k accumulators.

#define GRID   128
#define NTHR   256
#define BSZ    32
#define HID    2048
#define TIN    128
#define TOUT   64
#define TSTEPS 192
#define UPB    16
#define KC     128
#define NCH    16

// dynamic smem float offsets
#define SM_W   0            // 2 x 8192 floats (w chunk double buffer)
#define SM_H   16384        // 2 x 4096 floats (h chunk double buffer)
#define SM_GP  24576        // 16384 floats: [8 warp][64 cell][32 lane] (+ y-reduce scratch)
#define SM_GS  40960        // 2048 floats: gate sums [64 row][32 b] xor-swizzled
#define SM_YP  43008        // 16*33
#define SM_YS  43536        // 32
#define SM_X   43600        // 4096 floats: x transposed [t][b]
#define SM_WB  47696        // 128 floats: wih[4][16] + bias[4][16] for current phase
#define SM_FLOATS 47824     // 191296 B

__device__ __align__(16) float g_hA[BSZ * HID];
__device__ __align__(16) float g_hB[BSZ * HID];
__device__ float    g_yblk[GRID * BSZ];
__device__ unsigned g_bar, g_fin;

__device__ __forceinline__ void fma2(unsigned long long& d,
                                     unsigned long long a,
                                     unsigned long long b) {
    asm("fma.rn.f32x2 %0, %1, %2, %0;" : "+l"(d) : "l"(a), "l"(b));
}
__device__ __forceinline__ float hsum2(unsigned long long v) {
    return __uint_as_float((unsigned)v) + __uint_as_float((unsigned)(v >> 32));
}
__device__ __forceinline__ float sigmoidf(float v) { return 1.0f / (1.0f + __expf(-v)); }

__device__ __forceinline__ uint32_t smem_u32(const void* p) {
    uint32_t a;
    asm("{ .reg .u64 t; cvta.to.shared.u64 t, %1; cvt.u32.u64 %0, t; }" : "=r"(a) : "l"(p));
    return a;
}
__device__ __forceinline__ void cp16(uint32_t dst, const void* src) {
    asm volatile("cp.async.cg.shared.global [%0], [%1], 16;" :: "r"(dst), "l"(src));
}
#define CP_COMMIT() asm volatile("cp.async.commit_group;" ::: "memory")
#define CP_WAIT(n)  asm volatile("cp.async.wait_group %0;" :: "n"(n) : "memory")

__device__ __forceinline__ void grid_barrier(int n) {
    __syncthreads();
    if (threadIdx.x == 0) {
        __threadfence();
        atomicAdd(&g_bar, 1u);
        unsigned target = (unsigned)n * GRID, v;
        do {
            asm volatile("ld.acquire.gpu.global.u32 %0, [%1];" : "=r"(v) : "l"(&g_bar) : "memory");
        } while (v < target);
    }
    __syncthreads();
}

__global__ void __launch_bounds__(NTHR, 1)
lstm_seq2seq_kernel(const float* __restrict__ x,
                    const float* __restrict__ eWih, const float* __restrict__ eWhh,
                    const float* __restrict__ eb,
                    const float* __restrict__ dWih, const float* __restrict__ dWhh,
                    const float* __restrict__ db,
                    const float* __restrict__ fcW,  const float* __restrict__ fcb,
                    float* __restrict__ out) {
    extern __shared__ __align__(16) float smem[];
    const int tid  = threadIdx.x;
    const int blk  = blockIdx.x;
    const int wid  = tid >> 5;
    const int lane = tid & 31;
    const int rg   = lane >> 2;     // row group 0..7  (rows rg*8..rg*8+7)
    const int bg   = lane & 3;      // batch group 0..3 (batches bg*8..bg*8+7)
    const int ubase = blk * UPB;

    const uint32_t sw = smem_u32(smem + SM_W);
    const uint32_t sh = smem_u32(smem + SM_H);

    // cell-update ownership: cells (ul,b) = (wid, lane) and (wid+8, lane)
    const int cb = lane;
    float cst0 = 0.0f, cst1 = 0.0f;
    g_hA[cb * HID + ubase + wid]     = 0.0f;
    g_hA[cb * HID + ubase + wid + 8] = 0.0f;

    const float fcb0 = fcb[0];
    const float fcw0 = fcW[ubase + wid];
    const float fcw1 = fcW[ubase + wid + 8];

    // stage x transposed: xs[t*32 + b]
    #pragma unroll
    for (int i = 0; i < 16; ++i) {
        int id = tid + i * NTHR;            // 0..4095
        int b = id >> 7, tt = id & 127;
        smem[SM_X + tt * 32 + b] = x[id];
    }

    // prefetch w chunk 0 of step 0
    #pragma unroll
    for (int i = 0; i < 8; ++i) {
        int id = tid + i * NTHR;            // 0..2047
        int row = id >> 5, k4q = id & 31;
        int g = row >> 4, ul = row & 15;
        cp16(sw + (uint32_t)(row * 512 + ((k4q ^ (row >> 3)) << 4)),
             eWhh + (size_t)(g * HID + ubase + ul) * HID + k4q * 4);
    }
    CP_COMMIT();

    int bars = 0;
    grid_barrier(++bars);   // h init + x staging visible

    for (int t = 0; t < TSTEPS; ++t) {
        const bool enc = (t < TIN);
        if (t == 0 || t == TIN) {
            // per-phase Wih / bias table -> smem (64 + 64 floats)
            const float* Wih = enc ? eWih : dWih;
            const float* bia = enc ? eb   : db;
            if (tid < 64)
                smem[SM_WB + tid] = Wih[(tid >> 4) * HID + ubase + (tid & 15)];
            else if (tid < 128)
                smem[SM_WB + tid] = bia[((tid - 64) >> 4) * HID + ubase + (tid & 15)];
        }
        const float* Whh  = enc ? eWhh : dWhh;
        const float* hin  = (t & 1) ? g_hB : g_hA;
        float*       hout = (t & 1) ? g_hA : g_hB;

        // stage h chunk 0 first (async) so it overlaps the y-feedback reduce
        #pragma unroll
        for (int i = 0; i < 4; ++i) {
            int id = tid + i * NTHR;        // 0..1023
            int b = id >> 5, k4q = id & 31;
            cp16(sh + (uint32_t)(b * 512 + ((k4q ^ (b >> 3)) << 4)),
                 hin + b * HID + k4q * 4);
        }
        CP_COMMIT();

        // decoder feedback: reduce previous step's y partials (256-thread parallel)
        if (t > TIN) {
            const int yb = tid >> 3;        // batch 0..31
            const int yp = tid & 7;         // 16-block group 0..7
            float s = 0.0f;
            #pragma unroll
            for (int k = 0; k < 16; ++k)
                s += g_yblk[(yp * 16 + k) * BSZ + yb];
            smem[SM_GP + yb * 8 + yp] = s;  // GP region is free here
            __syncthreads();
            if (tid < BSZ) {
                float y = fcb0;
                #pragma unroll
                for (int p = 0; p < 8; ++p) y += smem[SM_GP + tid * 8 + p];
                smem[SM_YS + tid] = y;
                if (blk == 0) out[tid * TOUT + (t - 1 - TIN)] = y;
            }
            __syncthreads();
        }

        unsigned long long acc[8][8];
        #pragma unroll
        for (int i = 0; i < 8; ++i)
            #pragma unroll
            for (int j = 0; j < 8; ++j) acc[i][j] = 0ull;

        #pragma unroll 1
        for (int c = 0; c < NCH; ++c) {
            if (c + 1 < NCH) {
                const int cn = c + 1;
                const uint32_t wdst = sw + (uint32_t)((cn & 1) * 32768);
                const uint32_t hdst = sh + (uint32_t)((cn & 1) * 16384);
                #pragma unroll
                for (int i = 0; i < 8; ++i) {
                    int id = tid + i * NTHR;
                    int row = id >> 5, k4q = id & 31;
                    int g = row >> 4, ul = row & 15;
                    cp16(wdst + (uint32_t)(row * 512 + ((k4q ^ (row >> 3)) << 4)),
                         Whh + (size_t)(g * HID + ubase + ul) * HID + cn * KC + k4q * 4);
                }
                #pragma unroll
                for (int i = 0; i < 4; ++i) {
                    int id = tid + i * NTHR;
                    int b = id >> 5, k4q = id & 31;
                    cp16(hdst + (uint32_t)(b * 512 + ((k4q ^ (b >> 3)) << 4)),
                         hin + b * HID + cn * KC + k4q * 4);
                }
                CP_COMMIT();
                CP_WAIT(1);
            } else {
                CP_WAIT(0);
            }
            __syncthreads();

            const float* wb = smem + SM_W + (c & 1) * 8192;
            const float* hb = smem + SM_H + (c & 1) * 4096;
            #pragma unroll
            for (int q = 0; q < 4; ++q) {
                const int k4q = wid * 4 + q;
                #pragma unroll
                for (int jh = 0; jh < 2; ++jh) {
                    ulonglong2 hv[4];
                    #pragma unroll
                    for (int j = 0; j < 4; ++j)
                        hv[j] = *reinterpret_cast<const ulonglong2*>(
                            hb + (bg * 8 + jh * 4 + j) * 128 + ((k4q ^ bg) << 2));
                    #pragma unroll
                    for (int i = 0; i < 8; ++i) {
                        ulonglong2 wv = *reinterpret_cast<const ulonglong2*>(
                            wb + (rg * 8 + i) * 128 + ((k4q ^ rg) << 2));
                        #pragma unroll
                        for (int j = 0; j < 4; ++j) {
                            fma2(acc[i][jh * 4 + j], wv.x, hv[j].x);
                            fma2(acc[i][jh * 4 + j], wv.y, hv[j].y);
                        }
                    }
                }
            }
            __syncthreads();
        }

        // ---- epilogue ----
        // 1. per-warp partials -> smem
        {
            float* gp = smem + SM_GP + wid * 2048;
            #pragma unroll
            for (int i = 0; i < 8; ++i)
                #pragma unroll
                for (int j = 0; j < 8; ++j)
                    gp[(i * 8 + j) * 32 + lane] = hsum2(acc[i][j]);
        }
        __syncthreads();
        // 2. cross-warp k reduction -> gsum[row*32 + (b ^ (row>>3))]
        #pragma unroll
        for (int m = 0; m < 8; ++m) {
            int cp = tid + m * NTHR;
            float s = 0.0f;
            #pragma unroll
            for (int w = 0; w < 8; ++w) s += smem[SM_GP + w * 2048 + cp];
            int i = (cp >> 8) & 7, j = (cp >> 5) & 7, ln = cp & 31;
            int row = (ln >> 2) * 8 + i;
            int b   = (ln & 3) * 8 + j;
            smem[SM_GS + row * 32 + (b ^ (row >> 3))] = s;
        }
        __syncthreads();
        // 3. cell updates (2 per thread), c in registers; Wih/bias from smem
        {
            float inp;
            if (enc)            inp = smem[SM_X + t * 32 + cb];
            else if (t == TIN)  inp = smem[SM_X + (TIN - 1) * 32 + cb];
            else                inp = smem[SM_YS + cb];
            #pragma unroll
            for (int m = 0; m < 2; ++m) {
                const int ul = wid + m * 8;
                const int u  = ubase + ul;
                float gate[4];
                #pragma unroll
                for (int g = 0; g < 4; ++g) {
                    int row = g * 16 + ul;
                    gate[g] = smem[SM_GS + row * 32 + (cb ^ (row >> 3))]
                            + inp * smem[SM_WB + g * 16 + ul]
                            + smem[SM_WB + 64 + g * 16 + ul];
                }
                float iv = sigmoidf(gate[0]), fv = sigmoidf(gate[1]);
                float gv = tanhf(gate[2]),   ov = sigmoidf(gate[3]);
                float cold = m ? cst1 : cst0;
                float cn = fv * cold + iv * gv;
                if (m) cst1 = cn; else cst0 = cn;
                float hn = ov * tanhf(cn);
                hout[cb * HID + u] = hn;
                if (!enc) smem[SM_YP + ul * 33 + cb] = hn * (m ? fcw1 : fcw0);
            }
        }
        if (!enc) {
            __syncthreads();
            if (tid < BSZ) {
                float s = 0.0f;
                #pragma unroll
                for (int ul = 0; ul < UPB; ++ul) s += smem[SM_YP + ul * 33 + tid];
                g_yblk[blk * BSZ + tid] = s;
            }
        }

        // prefetch w chunk 0 of next step (buffer 0 is free: last used at c=14)
        if (t + 1 < TSTEPS) {
            const float* Wn = (t + 1 < TIN) ? eWhh : dWhh;
            #pragma unroll
            for (int i = 0; i < 8; ++i) {
                int id = tid + i * NTHR;
                int row = id >> 5, k4q = id & 31;
                int g = row >> 4, ul = row & 15;
                cp16(sw + (uint32_t)(row * 512 + ((k4q ^ (row >> 3)) << 4)),
                     Wn + (size_t)(g * HID + ubase + ul) * HID + k4q * 4);
            }
            CP_COMMIT();
        }
        grid_barrier(++bars);
    }

    // final output y_63
    if (blk == 0 && tid < BSZ) {
        float s = fcb0;
        #pragma unroll 8
        for (int g = 0; g < GRID; ++g) s += g_yblk[g * BSZ + tid];
        out[tid * TOUT + (TOUT - 1)] = s;
    }

    // barrier cleanup for graph replay
    __syncthreads();
    if (tid == 0) {
        unsigned o = atomicAdd(&g_fin, 1u);
        if (o == GRID - 1) { g_bar = 0u; g_fin = 0u; __threadfence(); }
    }
}

extern "C" void kernel_launch(void* const* d_in, const int* in_sizes, int n_in,
                              void* d_out, int out_size) {
    const float* x    = (const float*)d_in[0];
    const float* eWih = (const float*)d_in[2];
    const float* eWhh = (const float*)d_in[3];
    const float* eb   = (const float*)d_in[4];
    const float* dWih = (const float*)d_in[5];
    const float* dWhh = (const float*)d_in[6];
    const float* db   = (const float*)d_in[7];
    const float* fcW  = (const float*)d_in[8];
    const float* fcb  = (const float*)d_in[9];
    float* out = (float*)d_out;

    cudaFuncSetAttribute(lstm_seq2seq_kernel,
                         cudaFuncAttributeMaxDynamicSharedMemorySize,
                         SM_FLOATS * 4);
    lstm_seq2seq_kernel<<<GRID, NTHR, SM_FLOATS * 4>>>(
        x, eWih, eWhh, eb, dWih, dWhh, db, fcW, fcb, out);
}